// round 4
// baseline (speedup 1.0000x reference)
#include <cuda_runtime.h>
#include <cstdint>

#define SEQ 32
#define EDIM 256
#define HDIM 256
#define GDIM 1024
#define ROWS 32
#define NCTAS 128
#define NTHREADS 256
#define CLUSTER 4

#define XS 260   // smem row stride (floats) for x tile: conflict-free for (4*grp+tg)
#define HS 260

#define CHUNK_BYTES 32768          // one kb-slice of packed weights (all warps)
#define SLICE_BYTES 8192           // per-CTA multicast slice (CHUNK/4)
#define STAGES 4
#define CHUNKS_PER_STEP 64         // kb 0..31 = X part, 32..63 = H part
#define TOTAL_CHUNKS (SEQ*CHUNKS_PER_STEP)

#define WBUF_OFF 0
#define XS_OFF   (STAGES*CHUNK_BYTES)          // 131072
#define HB_OFF   (XS_OFF + ROWS*XS*4)          // 164352
#define BAR_OFF  (HB_OFF + 2*ROWS*HS*4)        // 230912
#define SMEM_BYTES (BAR_OFF + 64)              // 230976 <= 232448 opt-in

// Packed tf32 weights, chunked by kb:
// uint2 index = kb*4096 + (w*16 + nf)*32 + lane
__device__ __align__(16) uint2 g_wpk[CHUNKS_PER_STEP*8*16*32];
__device__ float g_bperm[GDIM];   // bias in gate-interleaved column space

__device__ __forceinline__ float tf32_round_f(float x) {
    float r;
    asm("cvt.rna.tf32.f32 %0, %1;" : "=f"(r) : "f"(x));
    return r;
}
__device__ __forceinline__ uint32_t tf32_round_u(float x) {
    uint32_t r;
    asm("cvt.rna.tf32.f32 %0, %1;" : "=r"(r) : "f"(x));
    return r;
}

#define MMA_TF32(d, a, b0, b1)                                              \
    asm volatile("mma.sync.aligned.m16n8k8.row.col.f32.tf32.tf32.f32 "      \
                 "{%0,%1,%2,%3}, {%4,%5,%6,%7}, {%8,%9}, {%0,%1,%2,%3};"    \
                 : "+f"((d)[0]), "+f"((d)[1]), "+f"((d)[2]), "+f"((d)[3])   \
                 : "r"((a)[0]), "r"((a)[1]), "r"((a)[2]), "r"((a)[3]),      \
                   "r"(b0), "r"(b1))

__device__ __forceinline__ uint32_t smem_u32(const void* p) {
    uint32_t a;
    asm("{ .reg .u64 t; cvta.to.shared.u64 t, %1; cvt.u32.u64 %0, t; }"
        : "=r"(a) : "l"(p));
    return a;
}
__device__ __forceinline__ uint32_t ctarank() {
    uint32_t r; asm("mov.u32 %0, %%cluster_ctarank;" : "=r"(r)); return r;
}

#define MBAR_INIT(addr, cnt) \
    asm volatile("mbarrier.init.shared.b64 [%0], %1;" :: "r"(addr), "r"(cnt) : "memory")
#define MBAR_EXPECT_TX(addr, bytes) \
    asm volatile("mbarrier.arrive.expect_tx.shared.b64 _, [%0], %1;" \
                 :: "r"(addr), "r"(bytes) : "memory")
#define MBAR_ARRIVE_RANK(addr, rnk)                                          \
    asm volatile("{\n\t.reg .b32 ra;\n\t"                                    \
                 "mapa.shared::cluster.u32 ra, %0, %1;\n\t"                  \
                 "mbarrier.arrive.shared::cluster.b64 _, [ra];\n\t}"         \
                 :: "r"(addr), "r"(rnk) : "memory")

#define MBAR_WAIT(addr, ph) do {                                             \
    uint32_t _m = (addr); uint32_t _p = (ph); uint32_t _done;                \
    asm volatile("{\n\t.reg .pred p;\n\t"                                    \
        "mbarrier.try_wait.parity.acquire.cta.shared::cta.b64 p, [%1], %2;\n\t" \
        "selp.b32 %0, 1, 0, p;\n\t}"                                         \
        : "=r"(_done) : "r"(_m), "r"(_p) : "memory");                        \
    if (!_done) {                                                            \
        asm volatile("{\n\t.reg .pred P1;\n\t"                               \
            "WL_%=:\n\t"                                                     \
            "mbarrier.try_wait.parity.acquire.cta.shared::cta.b64 P1, [%0], %1, 0x989680;\n\t" \
            "@P1 bra.uni WD_%=;\n\t"                                         \
            "bra.uni WL_%=;\n\t"                                             \
            "WD_%=:\n\t}" :: "r"(_m), "r"(_p) : "memory");                   \
    }                                                                        \
} while (0)

#define MBAR_WAIT_RELAXED(addr, ph) do {                                     \
    uint32_t _m = (addr); uint32_t _p = (ph); uint32_t _done;                \
    asm volatile("{\n\t.reg .pred p;\n\t"                                    \
        "mbarrier.try_wait.parity.relaxed.cta.shared::cta.b64 p, [%1], %2;\n\t" \
        "selp.b32 %0, 1, 0, p;\n\t}"                                         \
        : "=r"(_done) : "r"(_m), "r"(_p) : "memory");                        \
    if (!_done) {                                                            \
        asm volatile("{\n\t.reg .pred P1;\n\t"                               \
            "WL_%=:\n\t"                                                     \
            "mbarrier.try_wait.parity.relaxed.cta.shared::cta.b64 P1, [%0], %1, 0x989680;\n\t" \
            "@P1 bra.uni WD_%=;\n\t"                                         \
            "bra.uni WL_%=;\n\t"                                             \
            "WD_%=:\n\t}" :: "r"(_m), "r"(_p) : "memory");                   \
    }                                                                        \
} while (0)

#define CLUSTER_SYNC() do {                                                  \
    asm volatile("barrier.cluster.arrive.aligned;" ::: "memory");            \
    asm volatile("barrier.cluster.wait.aligned;" ::: "memory");              \
} while (0)

__device__ __forceinline__ void bulk_mcast(uint32_t dst_smem, const void* src,
                                           uint32_t bytes, uint32_t mbar,
                                           uint16_t mask) {
    asm volatile(
        "cp.async.bulk.shared::cluster.global.mbarrier::complete_tx::bytes"
        ".multicast::cluster [%0], [%1], %2, [%3], %4;"
        :: "r"(dst_smem), "l"(src), "r"(bytes), "r"(mbar), "h"(mask)
        : "memory");
}

// Prep: gate-interleave permutation + tf32 rounding + fragment packing (kb-chunked).
__global__ void prep_kernel(const float* __restrict__ wih,
                            const float* __restrict__ whh,
                            const float* __restrict__ bih,
                            const float* __restrict__ bhh) {
    int i = blockIdx.x * blockDim.x + threadIdx.x;   // 0..262143
    if (i >= CHUNKS_PER_STEP*8*16*32) return;
    int lane = i & 31;
    int nf   = (i >> 5) & 15;
    int w    = (i >> 9) & 7;
    int kb   = i >> 12;
    int grp  = lane >> 2;
    int tg   = lane & 3;

    int colperm = w*128 + nf*8 + grp;
    int unit = colperm >> 2;
    int gate = colperm & 3;
    int orow = gate*256 + unit;
    int kk   = (kb & 31)*8 + tg;
    const float* W = (kb < 32) ? wih : whh;

    uint2 v;
    v.x = tf32_round_u(W[orow*256 + kk]);
    v.y = tf32_round_u(W[orow*256 + kk + 4]);
    g_wpk[i] = v;

    if (i < GDIM) {
        int u2 = i >> 2, g2 = i & 3;
        g_bperm[i] = bih[g2*256 + u2] + bhh[g2*256 + u2];
    }
}

__device__ __forceinline__ float sigmoidf_(float x) {
    return 1.0f / (1.0f + __expf(-x));
}

__global__ __launch_bounds__(NTHREADS, 1) __cluster_dims__(CLUSTER, 1, 1)
void lstm_fused_kernel(const float* __restrict__ x, float* __restrict__ out) {
    extern __shared__ char smem[];
    const uint32_t sb = smem_u32(smem);
    float* Xs = (float*)(smem + XS_OFF);
    float* Hb = (float*)(smem + HB_OFF);
    const uint32_t full_bar  = sb + BAR_OFF;        // 4 x 8B
    const uint32_t empty_bar = sb + BAR_OFF + 32;   // 4 x 8B

    const int tid  = threadIdx.x;
    const int lane = tid & 31;
    const int w    = tid >> 5;
    const int grp  = lane >> 2;
    const int tg   = lane & 3;
    const int tgl  = tg & 1;
    const int tgh  = tg >> 1;
    const uint32_t rank = ctarank();
    const long rowbase = (long)blockIdx.x * ROWS;
    const char* wsrc = (const char*)g_wpk;

    // init barriers
    if (tid == 0) {
        #pragma unroll
        for (int st = 0; st < STAGES; ++st) {
            MBAR_INIT(full_bar + 8*st, 1);                 // 1 expect_tx arrive
            MBAR_INIT(empty_bar + 8*st, 8*CLUSTER);        // 8 warps x 4 CTAs
        }
    }
    // zero h buffer 0 (s=0 H-part becomes a no-op)
    for (int i = tid; i < ROWS*HS; i += NTHREADS) Hb[i] = 0.0f;
    __syncthreads();
    CLUSTER_SYNC();   // all barriers visible before any multicast targets them

    // prologue: fill stages 0..3
    if (tid == 0) {
        #pragma unroll
        for (int c0 = 0; c0 < STAGES; ++c0) {
            MBAR_EXPECT_TX(full_bar + 8*c0, CHUNK_BYTES);
            bulk_mcast(sb + WBUF_OFF + c0*CHUNK_BYTES + rank*SLICE_BYTES,
                       wsrc + (size_t)c0*CHUNK_BYTES + rank*SLICE_BYTES,
                       SLICE_BYTES, full_bar + 8*c0, (uint16_t)0xF);
        }
    }

    // c-state in registers
    float cst[2][16];
    #pragma unroll
    for (int a = 0; a < 2; ++a)
        #pragma unroll
        for (int b = 0; b < 16; ++b) cst[a][b] = 0.0f;

    const float* xbase = x + rowbase * (SEQ*EDIM);
    int c = 0;   // global chunk counter

    for (int s = 0; s < SEQ; ++s) {
        // ---- stage x_s tile [32][256] (tf32-rounded) ----
        {
            const long srow = (long)s * EDIM;
            #pragma unroll
            for (int it = 0; it < 8; ++it) {
                int fi = tid + it * NTHREADS;
                int r  = fi >> 6;
                int cq = fi & 63;
                const float4 v = *((const float4*)(xbase + (long)r*(SEQ*EDIM) + srow) + cq);
                float* dst = &Xs[r*XS + cq*4];
                dst[0] = tf32_round_f(v.x);
                dst[1] = tf32_round_f(v.y);
                dst[2] = tf32_round_f(v.z);
                dst[3] = tf32_round_f(v.w);
            }
        }
        __syncthreads();

        const float* Hcur = Hb + (s & 1) * ROWS*HS;
        float*       Hnxt = Hb + ((s + 1) & 1) * ROWS*HS;

        // accumulators: [mh][nf][4], bias-initialized
        float d[2][16][4];
        #pragma unroll
        for (int nf = 0; nf < 16; ++nf) {
            int col = w*128 + nf*8 + 2*tg;
            float b0v = g_bperm[col], b1v = g_bperm[col + 1];
            d[0][nf][0] = b0v; d[0][nf][1] = b1v; d[0][nf][2] = b0v; d[0][nf][3] = b1v;
            d[1][nf][0] = b0v; d[1][nf][1] = b1v; d[1][nf][2] = b0v; d[1][nf][3] = b1v;
        }

        #pragma unroll 1
        for (int kb = 0; kb < CHUNKS_PER_STEP; ++kb, ++c) {
            const int stage = c & 3;
            MBAR_WAIT(full_bar + 8*stage, (c >> 2) & 1);

            const uint32_t* A = (const uint32_t*)((kb < 32) ? Xs : Hcur);
            const int k8 = (kb & 31) * 8;
            uint32_t a0[4], a1[4];
            a0[0] = A[grp*XS + k8 + tg];
            a0[1] = A[(grp+8)*XS + k8 + tg];
            a0[2] = A[grp*XS + k8 + 4 + tg];
            a0[3] = A[(grp+8)*XS + k8 + 4 + tg];
            a1[0] = A[(grp+16)*XS + k8 + tg];
            a1[1] = A[(grp+24)*XS + k8 + tg];
            a1[2] = A[(grp+16)*XS + k8 + 4 + tg];
            a1[3] = A[(grp+24)*XS + k8 + 4 + tg];

            const uint2* bp = (const uint2*)(smem + WBUF_OFF + stage*CHUNK_BYTES)
                              + (w*16)*32 + lane;
            #pragma unroll
            for (int nf = 0; nf < 16; ++nf) {
                uint2 b = bp[nf*32];
                MMA_TF32(d[0][nf], a0, b.x, b.y);
                MMA_TF32(d[1][nf], a1, b.x, b.y);
            }

            // release this stage cluster-wide (one lane per warp, all 4 ranks)
            if (lane == 0) {
                #pragma unroll
                for (int r = 0; r < CLUSTER; ++r)
                    MBAR_ARRIVE_RANK(empty_bar + 8*stage, r);
            }

            // rotating producer refills stage for chunk c+4
            const int cn = c + STAGES;
            if (cn < TOTAL_CHUNKS && w == (cn & 7) && lane == 0) {
                const int pst = cn & 3;
                MBAR_WAIT_RELAXED(empty_bar + 8*pst, ((cn >> 2) + 1) & 1);
                MBAR_EXPECT_TX(full_bar + 8*pst, CHUNK_BYTES);
                bulk_mcast(sb + WBUF_OFF + pst*CHUNK_BYTES + rank*SLICE_BYTES,
                           wsrc + (size_t)(cn & 63)*CHUNK_BYTES + rank*SLICE_BYTES,
                           SLICE_BYTES, full_bar + 8*pst, (uint16_t)0xF);
            }
        }

        // ---- activation in registers ----
        #pragma unroll
        for (int mh = 0; mh < 2; ++mh) {
            #pragma unroll
            for (int nf = 0; nf < 16; ++nf) {
                float c0 = d[mh][nf][0], c1 = d[mh][nf][1];
                float c2 = d[mh][nf][2], c3 = d[mh][nf][3];
                float x0 = __shfl_xor_sync(0xffffffffu, tgl ? c0 : c2, 1);
                float x1 = __shfl_xor_sync(0xffffffffu, tgl ? c1 : c3, 1);
                float gi = tgl ? x0 : c0;
                float gf = tgl ? x1 : c1;
                float gg = tgl ? c2 : x0;
                float go = tgl ? c3 : x1;
                int row  = mh*16 + grp + 8*tgl;
                int u    = w*32 + 2*nf + tgh;
                float cv = sigmoidf_(gf) * cst[mh][nf]
                         + sigmoidf_(gi) * tanhf(gg);
                cst[mh][nf] = cv;
                float h = sigmoidf_(go) * tanhf(cv);
                Hnxt[row*HS + u] = tf32_round_f(h);
                if (s == SEQ - 1) out[(rowbase + row)*HDIM + u] = h;
            }
        }
        __syncthreads();
    }

    CLUSTER_SYNC();   // no CTA exits while peers may still multicast into it
}

extern "C" void kernel_launch(void* const* d_in, const int* in_sizes, int n_in,
                              void* d_out, int out_size) {
    const float* x   = (const float*)d_in[0];
    const float* wih = (const float*)d_in[1];
    const float* whh = (const float*)d_in[2];
    const float* bih = (const float*)d_in[3];
    const float* bhh = (const float*)d_in[4];
    float* out = (float*)d_out;

    cudaFuncSetAttribute(lstm_fused_kernel,
                         cudaFuncAttributeMaxDynamicSharedMemorySize, SMEM_BYTES);

    prep_kernel<<<(CHUNKS_PER_STEP*8*16*32 + 255)/256, 256>>>(wih, whh, bih, bhh);
    lstm_fused_kernel<<<NCTAS, NTHREADS, SMEM_BYTES>>>(x, out);
}

// round 5
// speedup vs baseline: 1.7586x; 1.7586x over previous
#include <cuda_runtime.h>
#include <cstdint>

#define SEQ 32
#define EDIM 256
#define HDIM 256
#define GDIM 1024
#define ROWS 32
#define NCTAS 128
#define NTHREADS 512
#define NWARPS 16

#define XS 260   // smem row stride (floats): conflict-free for (4*grp+tg) lane pattern
#define HS 260
#define SMEM_FLOATS (ROWS*XS + 2*ROWS*HS)
#define SMEM_BYTES (SMEM_FLOATS*4)   // 99,840 B

// Packed tf32 weights in per-lane MMA B-fragment order:
// index = (((w*64 + kb)*8 + nf)*32 + lane), w = warp 0..15 (64-col slice),
// kb 0..31 = X part, 32..63 = H part
__device__ __align__(16) uint2 g_wpk[NWARPS*64*8*32];
__device__ float g_bperm[GDIM];   // bias in gate-interleaved (permuted) column space

__device__ __forceinline__ float tf32_round_f(float x) {
    float r;
    asm("cvt.rna.tf32.f32 %0, %1;" : "=f"(r) : "f"(x));
    return r;
}
__device__ __forceinline__ uint32_t tf32_round_u(float x) {
    uint32_t r;
    asm("cvt.rna.tf32.f32 %0, %1;" : "=r"(r) : "f"(x));
    return r;
}

#define MMA_TF32(d, a, b0, b1)                                              \
    asm volatile("mma.sync.aligned.m16n8k8.row.col.f32.tf32.tf32.f32 "      \
                 "{%0,%1,%2,%3}, {%4,%5,%6,%7}, {%8,%9}, {%0,%1,%2,%3};"    \
                 : "+f"((d)[0]), "+f"((d)[1]), "+f"((d)[2]), "+f"((d)[3])   \
                 : "r"((a)[0]), "r"((a)[1]), "r"((a)[2]), "r"((a)[3]),      \
                   "r"(b0), "r"(b1))

// Prep: gate-interleave permutation + tf32 rounding + fragment packing.
// Permuted col p: unit u = p>>2, gate g = p&3, original W row = g*256 + u.
__global__ void prep_kernel(const float* __restrict__ wih,
                            const float* __restrict__ whh,
                            const float* __restrict__ bih,
                            const float* __restrict__ bhh) {
    int i = blockIdx.x * blockDim.x + threadIdx.x;   // 0..262143
    if (i >= NWARPS*64*8*32) return;
    int lane = i & 31;
    int nf   = (i >> 5) & 7;
    int kb   = (i >> 8) & 63;
    int w    = i >> 14;          // 0..15
    int grp  = lane >> 2;
    int tg   = lane & 3;

    int colperm = w*64 + nf*8 + grp;
    int unit = colperm >> 2;
    int gate = colperm & 3;
    int orow = gate*256 + unit;
    int kk   = (kb & 31)*8 + tg;
    const float* W = (kb < 32) ? wih : whh;

    uint2 v;
    v.x = tf32_round_u(W[orow*256 + kk]);
    v.y = tf32_round_u(W[orow*256 + kk + 4]);
    g_wpk[i] = v;

    if (i < GDIM) {
        int u2 = i >> 2, g2 = i & 3;
        g_bperm[i] = bih[g2*256 + u2] + bhh[g2*256 + u2];
    }
}

__device__ __forceinline__ float sigmoidf_(float x) {
    return 1.0f / (1.0f + __expf(-x));
}

__global__ __launch_bounds__(NTHREADS, 1)
void lstm_fused_kernel(const float* __restrict__ x, float* __restrict__ out) {
    extern __shared__ float sm[];
    float* Xs = sm;               // [32][XS], tf32-rounded x_s tile
    float* Hb = Xs + ROWS*XS;     // two ping-pong h buffers [32][HS], tf32-rounded

    const int tid  = threadIdx.x;
    const int lane = tid & 31;
    const int w    = tid >> 5;    // 0..15
    const int grp  = lane >> 2;
    const int tg   = lane & 3;
    const int tgl  = tg & 1;
    const int tgh  = tg >> 1;
    const long rowbase = (long)blockIdx.x * ROWS;

    // c-state in registers: [mh][nf]
    float cst[2][8];
    #pragma unroll
    for (int a = 0; a < 2; ++a)
        #pragma unroll
        for (int b = 0; b < 8; ++b) cst[a][b] = 0.0f;

    const float* xbase = x + rowbase * (SEQ*EDIM);

    for (int s = 0; s < SEQ; ++s) {
        // ---- stage x_s tile [32][256] (tf32-rounded) ----
        {
            const long srow = (long)s * EDIM;
            #pragma unroll
            for (int it = 0; it < 4; ++it) {
                int fi = tid + it * NTHREADS;    // 0..2047 float4 index
                int r  = fi >> 6;
                int cq = fi & 63;
                const float4 v = *((const float4*)(xbase + (long)r*(SEQ*EDIM) + srow) + cq);
                float* dst = &Xs[r*XS + cq*4];
                dst[0] = tf32_round_f(v.x);
                dst[1] = tf32_round_f(v.y);
                dst[2] = tf32_round_f(v.z);
                dst[3] = tf32_round_f(v.w);
            }
        }
        __syncthreads();

        const float* Hcur = Hb + (s & 1) * ROWS*HS;
        float*       Hnxt = Hb + ((s + 1) & 1) * ROWS*HS;
        const bool doH = (s > 0);

        const int nbase = w * 64;
        const int ubase = nbase >> 2;
        float d[2][8][4];
        #pragma unroll
        for (int nf = 0; nf < 8; ++nf) {
            int col = nbase + nf*8 + 2*tg;
            float b0v = g_bperm[col], b1v = g_bperm[col + 1];
            d[0][nf][0] = b0v; d[0][nf][1] = b1v; d[0][nf][2] = b0v; d[0][nf][3] = b1v;
            d[1][nf][0] = b0v; d[1][nf][1] = b1v; d[1][nf][2] = b0v; d[1][nf][3] = b1v;
        }

        const uint2* wp = g_wpk + ((long)w * 64 * 8) * 32 + lane;

        // X part: K = 0..255
        {
            const uint32_t* A = (const uint32_t*)Xs;
            #pragma unroll 4
            for (int kb = 0; kb < 32; ++kb) {
                const int k8 = kb*8;
                uint32_t a[2][4];
                #pragma unroll
                for (int mh = 0; mh < 2; ++mh) {
                    int r0 = mh*16 + grp;
                    a[mh][0] = A[r0*XS + k8 + tg];
                    a[mh][1] = A[(r0+8)*XS + k8 + tg];
                    a[mh][2] = A[r0*XS + k8 + 4 + tg];
                    a[mh][3] = A[(r0+8)*XS + k8 + 4 + tg];
                }
                #pragma unroll
                for (int nf = 0; nf < 8; ++nf) {
                    uint2 b = wp[(kb*8 + nf)*32];
                    MMA_TF32(d[0][nf], a[0], b.x, b.y);
                    MMA_TF32(d[1][nf], a[1], b.x, b.y);
                }
            }
        }
        // H part: K = 256..511 (Hcur already tf32-rounded)
        if (doH) {
            const uint32_t* A = (const uint32_t*)Hcur;
            #pragma unroll 4
            for (int kb = 0; kb < 32; ++kb) {
                const int k8 = kb*8;
                uint32_t a[2][4];
                #pragma unroll
                for (int mh = 0; mh < 2; ++mh) {
                    int r0 = mh*16 + grp;
                    a[mh][0] = A[r0*HS + k8 + tg];
                    a[mh][1] = A[(r0+8)*HS + k8 + tg];
                    a[mh][2] = A[r0*HS + k8 + 4 + tg];
                    a[mh][3] = A[(r0+8)*HS + k8 + 4 + tg];
                }
                #pragma unroll
                for (int nf = 0; nf < 8; ++nf) {
                    uint2 b = wp[((32 + kb)*8 + nf)*32];
                    MMA_TF32(d[0][nf], a[0], b.x, b.y);
                    MMA_TF32(d[1][nf], a[1], b.x, b.y);
                }
            }
        }

        // ---- activation in registers ----
        // even tg-lane handles row grp+16mh; odd tg-lane handles row grp+8+16mh.
        #pragma unroll
        for (int mh = 0; mh < 2; ++mh) {
            #pragma unroll
            for (int nf = 0; nf < 8; ++nf) {
                float c0 = d[mh][nf][0], c1 = d[mh][nf][1];
                float c2 = d[mh][nf][2], c3 = d[mh][nf][3];
                float x0 = __shfl_xor_sync(0xffffffffu, tgl ? c0 : c2, 1);
                float x1 = __shfl_xor_sync(0xffffffffu, tgl ? c1 : c3, 1);
                float gi = tgl ? x0 : c0;
                float gf = tgl ? x1 : c1;
                float gg = tgl ? c2 : x0;
                float go = tgl ? c3 : x1;
                int row  = grp + 8*tgl + 16*mh;
                int u    = ubase + 2*nf + tgh;
                float cv = sigmoidf_(gf) * cst[mh][nf]
                         + sigmoidf_(gi) * tanhf(gg);
                cst[mh][nf] = cv;
                float h = sigmoidf_(go) * tanhf(cv);
                Hnxt[row*HS + u] = tf32_round_f(h);
                if (s == SEQ - 1) out[(rowbase + row)*HDIM + u] = h;
            }
        }
        __syncthreads();
    }
}

extern "C" void kernel_launch(void* const* d_in, const int* in_sizes, int n_in,
                              void* d_out, int out_size) {
    const float* x   = (const float*)d_in[0];
    const float* wih = (const float*)d_in[1];
    const float* whh = (const float*)d_in[2];
    const float* bih = (const float*)d_in[3];
    const float* bhh = (const float*)d_in[4];
    float* out = (float*)d_out;

    cudaFuncSetAttribute(lstm_fused_kernel,
                         cudaFuncAttributeMaxDynamicSharedMemorySize, SMEM_BYTES);

    prep_kernel<<<(NWARPS*64*8*32 + 255)/256, 256>>>(wih, whh, bih, bhh);
    lstm_fused_kernel<<<NCTAS, NTHREADS, SMEM_BYTES>>>(x, out);
}